// round 1
// baseline (speedup 1.0000x reference)
#include <cuda_runtime.h>
#include <math.h>
#include <stdint.h>

// ---------------- problem constants (fixed by setup_inputs) ----------------
#define NN 4096
#define LL 256
#define TLGT 128

static __device__ __constant__ const float kDummy = 0.f; // (unused)

constexpr float MUv     = 1e-3f;
constexpr float ONEMMU  = 1.0f - 1e-3f;
constexpr float NE      = 4.0f * 10000.0f / 4096.0f;   // 9.765625
constexpr float INV_NM1 = 1.0f / 4095.0f;
constexpr float EPSF    = 2.2204460492503131e-16f;      // float64 eps, as f32

// ---------------- scratch (device globals: no allocation allowed) ----------
__device__ float g_alpha[(size_t)NN * NN];   // 64 MB
__device__ float g_beta [(size_t)NN * NN];   // 64 MB
__device__ float g_cs[3][NN];                // rotating colsum / denom buffers
__device__ int   g_cnt[2];                   // popcount of h[0], h[L-1]

// ---------------- tiling ----------------
constexpr int CPB = 256;   // columns per block == blockDim.x
constexpr int RPB = 128;   // rows per block

__device__ __forceinline__ float clip01(float x) {
    return fminf(fmaxf(x, 0.0f), 1.0f);
}

// ---------------- popcount of two h rows ----------------
__global__ void k_popcnt(const int* __restrict__ h) {
    int row = blockIdx.x ? (LL - 1) : 0;
    const int* hr = h + (size_t)row * NN;
    int t = threadIdx.x;
    int s = 0;
    for (int i = t; i < NN; i += 256) s += hr[i];
    __shared__ int sm[256];
    sm[t] = s;
    __syncthreads();
    for (int st = 128; st > 0; st >>= 1) {
        if (t < st) sm[t] += sm[t + st];
        __syncthreads();
    }
    if (t == 0) g_cnt[blockIdx.x] = sm[0];
}

// analytic colsum/denom of the binary-emission initial matrix:
//   dst[j] = sum_{i != j} theta(h[row][i], h[row][j]) / (N-1)
__global__ void k_init_cs(const int* __restrict__ h, int row, int cntIdx,
                          int dstIdx, int zeroIdx) {
    int j = blockIdx.x * 256 + threadIdx.x;
    int hj = h[(size_t)row * NN + j];
    int c = g_cnt[cntIdx];
    int match = hj ? (c - 1) : (NN - 1 - c);
    int mism  = (NN - 1) - match;
    g_cs[dstIdx][j]  = ((float)match * ONEMMU + (float)mism * MUv) * INV_NM1;
    g_cs[zeroIdx][j] = 0.0f;
}

// alpha0[i,j] = theta0(i,j)/(N-1), diag 0
__global__ __launch_bounds__(CPB) void k_alpha0(const int* __restrict__ h) {
    __shared__ int sh[RPB];
    int tid = threadIdx.x;
    int j  = blockIdx.x * CPB + tid;
    int i0 = blockIdx.y * RPB;
    if (tid < RPB) sh[tid] = h[i0 + tid];
    int hj = h[j];
    __syncthreads();
    float* ap = g_alpha + (size_t)i0 * NN + j;
#pragma unroll 8
    for (int ii = 0; ii < RPB; ii++) {
        float v = ((sh[ii] == hj) ? ONEMMU : MUv) * INV_NM1;
        if (i0 + ii == j) v = 0.0f;
        ap[(size_t)ii * NN] = v;
    }
}

// forward step l (1..TLGT):
//   a = alpha/colsum_prev ; a = (1-r)a + r*pi ; a = theta_l * a * offdiag
// fused: accumulate next colsum while writing.
__global__ __launch_bounds__(CPB) void k_fwd(const int* __restrict__ h,
                                             const float* __restrict__ m,
                                             int l, int rd, int wr, int zr) {
    __shared__ int sh[RPB];
    int tid = threadIdx.x;
    int j  = blockIdx.x * CPB + tid;
    int i0 = blockIdx.y * RPB;
    const int* hr = h + (size_t)l * NN;
    if (tid < RPB) sh[tid] = hr[i0 + tid];
    if (blockIdx.y == 0) g_cs[zr][j] = 0.0f;   // prep buffer for step l+2
    float r    = -expm1f(-NE * m[l - 1]);
    int   hj   = hr[j];
    float coef = (1.0f - r) / g_cs[rd][j];
    float addc = r * INV_NM1;
    __syncthreads();
    float acc = 0.0f;
    float* ap = g_alpha + (size_t)i0 * NN + j;
#pragma unroll 8
    for (int ii = 0; ii < RPB; ii++) {
        float v = fmaf(ap[(size_t)ii * NN], coef, addc);
        v *= (sh[ii] == hj) ? ONEMMU : MUv;
        if (i0 + ii == j) v = 0.0f;
        ap[(size_t)ii * NN] = v;
        acc += v;
    }
    atomicAdd(&g_cs[wr][j], acc);
}

// backward step l (254..128): b = theta_{l+1}*beta ; beta = ((1-r)b/denom + r)*offdiag
// fused: accumulate next denom ( sum_i theta_l * beta_new * pi ) while writing.
__global__ __launch_bounds__(CPB) void k_bwd(const int* __restrict__ h,
                                             const float* __restrict__ m,
                                             int l, int first,
                                             int rd, int wr, int zr) {
    __shared__ int sh1[RPB], sh0[RPB];
    int tid = threadIdx.x;
    int j  = blockIdx.x * CPB + tid;
    int i0 = blockIdx.y * RPB;
    const int* hr1 = h + (size_t)(l + 1) * NN;
    const int* hr0 = h + (size_t)l * NN;
    if (tid < RPB) { sh1[tid] = hr1[i0 + tid]; sh0[tid] = hr0[i0 + tid]; }
    if (blockIdx.y == 0) g_cs[zr][j] = 0.0f;
    float r    = -expm1f(-NE * m[l]);
    int   hj1  = hr1[j];
    int   hj0  = hr0[j];
    float coef = (1.0f - r) / g_cs[rd][j];
    __syncthreads();
    float acc = 0.0f;
    float* bp = g_beta + (size_t)i0 * NN + j;
#pragma unroll 8
    for (int ii = 0; ii < RPB; ii++) {
        float bprev = first ? 1.0f : bp[(size_t)ii * NN];
        float b = ((sh1[ii] == hj1) ? ONEMMU : MUv) * bprev;
        float v = fmaf(b, coef, r);
        if (i0 + ii == j) v = 0.0f;
        bp[(size_t)ii * NN] = v;
        acc = fmaf((sh0[ii] == hj0) ? ONEMMU : MUv, v, acc);
    }
    atomicAdd(&g_cs[wr][j], acc * INV_NM1);
}

// psum[j] = sum_i clip01(alpha)*clip01(beta)   (into g_cs[2], zeroed by last bwd step)
__global__ __launch_bounds__(CPB) void k_psum() {
    int tid = threadIdx.x;
    int j  = blockIdx.x * CPB + tid;
    int i0 = blockIdx.y * RPB;
    const float* ap = g_alpha + (size_t)i0 * NN + j;
    const float* bp = g_beta  + (size_t)i0 * NN + j;
    float acc = 0.0f;
#pragma unroll 8
    for (int ii = 0; ii < RPB; ii++) {
        acc += clip01(ap[(size_t)ii * NN]) * clip01(bp[(size_t)ii * NN]);
    }
    atomicAdd(&g_cs[2][j], acc);
}

// p = clip(a)*clip(b)/psum[j] -> out[0..N^2);  also emit alpha,beta copies.
__global__ __launch_bounds__(CPB) void k_post(float* __restrict__ out, size_t osz) {
    int tid = threadIdx.x;
    int j  = blockIdx.x * CPB + tid;
    int i0 = blockIdx.y * RPB;
    float psinv = 1.0f / g_cs[2][j];
    const size_t NSQ = (size_t)NN * NN;
#pragma unroll 4
    for (int ii = 0; ii < RPB; ii++) {
        size_t o = (size_t)(i0 + ii) * NN + j;
        float a = g_alpha[o];
        float b = g_beta[o];
        float pr = clip01(a) * clip01(b) * psinv;
        if (o < osz)            out[o] = pr;
        if (2 * NSQ + o < osz)  out[2 * NSQ + o] = a;
        if (3 * NSQ + o < osz)  out[3 * NSQ + o] = b;
    }
}

// d[i,j] = -0.5*(log pc[i,j] + log pc[j,i]) * offdiag, tiled transpose
__global__ void k_dist(const float* __restrict__ p, float* __restrict__ d,
                       size_t dmax) {
    __shared__ float tp[32][33];
    int tx = threadIdx.x, ty = threadIdx.y;    // 32 x 8
    int bi = blockIdx.y, bj = blockIdx.x;
#pragma unroll
    for (int k = 0; k < 4; k++) {
        int r = bj * 32 + ty + 8 * k;          // source row = j-range
        int c = bi * 32 + tx;                  // source col = i-range
        tp[ty + 8 * k][tx] = logf(fmaxf(p[(size_t)r * NN + c], EPSF));
    }
    __syncthreads();
#pragma unroll
    for (int k = 0; k < 4; k++) {
        int i = bi * 32 + ty + 8 * k;
        int j = bj * 32 + tx;
        float lp  = logf(fmaxf(p[(size_t)i * NN + j], EPSF));
        float lpt = tp[tx][ty + 8 * k];        // log pc[j,i]
        float v = (i == j) ? 0.0f : -0.5f * (lp + lpt);
        size_t o = (size_t)i * NN + j;
        if (o < dmax) d[o] = v;
    }
}

// ---------------- launcher ----------------
extern "C" void kernel_launch(void* const* d_in, const int* in_sizes, int n_in,
                              void* d_out, int out_size) {
    const int*   h = (const int*)d_in[0];
    const float* m = (const float*)d_in[1];
    float* out = (float*)d_out;
    size_t osz = (size_t)out_size;
    const size_t NSQ = (size_t)NN * NN;

    dim3 grid(NN / CPB, NN / RPB);   // 16 x 32 = 512 blocks

    // ---- forward ----
    k_popcnt<<<2, 256>>>(h);
    k_init_cs<<<NN / 256, 256>>>(h, 0, 0, /*dst=*/1, /*zero=*/2);
    k_alpha0<<<grid, CPB>>>(h);
    for (int l = 1; l <= TLGT; l++) {
        k_fwd<<<grid, CPB>>>(h, m, l, l % 3, (l + 1) % 3, (l + 2) % 3);
    }

    // ---- backward ----
    k_init_cs<<<NN / 256, 256>>>(h, LL - 1, 1, /*dst=*/0, /*zero=*/1);
    const int nb = LL - 1 - TLGT;   // 127 steps
    for (int t = 0; t < nb; t++) {
        int l = LL - 2 - t;
        k_bwd<<<grid, CPB>>>(h, m, l, (t == 0) ? 1 : 0,
                             t % 3, (t + 1) % 3, (t + 2) % 3);
    }

    // ---- posterior + distance ----
    // g_cs[2] was zeroed by the last bwd step's zero-duty ( (126+2)%3 == 2 ).
    k_psum<<<grid, CPB>>>();
    k_post<<<grid, CPB>>>(out, osz);
    if (osz > NSQ) {
        k_dist<<<dim3(NN / 32, NN / 32), dim3(32, 8)>>>(out, out + NSQ,
                                                        osz - NSQ);
    }
}